// round 4
// baseline (speedup 1.0000x reference)
#include <cuda_runtime.h>
#include <cuda_bf16.h>
#include <cstddef>

// Problem constants
#define T_SEQ 2048
#define C_DIM 768
#define N_HEAD 12
#define D_HEAD 64
#define D_HID 3072

// ---------------------------------------------------------------------------
// Scratch (no cudaMalloc allowed)
// ---------------------------------------------------------------------------
__device__ float g_h  [T_SEQ * C_DIM];
__device__ float g_q  [T_SEQ * C_DIM];
__device__ float g_k  [T_SEQ * C_DIM];
__device__ float g_q2 [T_SEQ * C_DIM];
__device__ float g_k2 [T_SEQ * C_DIM];
__device__ float g_v  [T_SEQ * C_DIM];
__device__ float g_z  [T_SEQ * C_DIM];
__device__ float g_x1 [T_SEQ * C_DIM];
__device__ float g_h2 [T_SEQ * C_DIM];
__device__ float g_t1 [T_SEQ * D_HID];
__device__ float g_hid[T_SEQ * D_HID];

// ---------------------------------------------------------------------------
// RMSNorm: one block per token
// ---------------------------------------------------------------------------
__global__ void rms_kernel(const float* __restrict__ x, float* __restrict__ o)
{
    const int t = blockIdx.x;
    const float* xr = x + (size_t)t * C_DIM;
    float s = 0.f;
    for (int i = threadIdx.x; i < C_DIM; i += 256) {
        float v = xr[i];
        s += v * v;
    }
    #pragma unroll
    for (int off = 16; off; off >>= 1)
        s += __shfl_down_sync(0xffffffffu, s, off);
    __shared__ float ws[8];
    __shared__ float scale_s;
    if ((threadIdx.x & 31) == 0) ws[threadIdx.x >> 5] = s;
    __syncthreads();
    if (threadIdx.x == 0) {
        float tot = 0.f;
        #pragma unroll
        for (int w = 0; w < 8; w++) tot += ws[w];
        scale_s = rsqrtf(tot * (1.0f / C_DIM) + 1e-6f);
    }
    __syncthreads();
    const float sc = scale_s;
    for (int i = threadIdx.x; i < C_DIM; i += 256)
        o[(size_t)t * C_DIM + i] = xr[i] * sc;
}

// ---------------------------------------------------------------------------
// RoPE in-place on q,k,q2,k2.  grid = T, block = H*32 = 384
// ---------------------------------------------------------------------------
__global__ void rope_kernel(float* __restrict__ q, float* __restrict__ k,
                            float* __restrict__ q2, float* __restrict__ k2)
{
    const int t = blockIdx.x;
    const int p = threadIdx.x;        // 0..383
    const int h = p >> 5;
    const int i = p & 31;
    // inv_freq = 10000^(-i/32) = exp(-i * ln(10000)/32)
    const float inv = expf(-(float)i * (9.210340371976184f / 32.0f));
    const float ang = (float)t * inv;
    float sn, cs;
    sincosf(ang, &sn, &cs);
    const size_t base = (size_t)t * C_DIM + h * D_HEAD;
    {
        float a = q[base + i], b = q[base + 32 + i];
        q[base + i]      = a * cs + b * sn;
        q[base + 32 + i] = -a * sn + b * cs;
    }
    {
        float a = k[base + i], b = k[base + 32 + i];
        k[base + i]      = a * cs + b * sn;
        k[base + 32 + i] = -a * sn + b * cs;
    }
    {
        float a = q2[base + i], b = q2[base + 32 + i];
        q2[base + i]      = a * cs + b * sn;
        q2[base + 32 + i] = -a * sn + b * cs;
    }
    {
        float a = k2[base + i], b = k2[base + 32 + i];
        k2[base + i]      = a * cs + b * sn;
        k2[base + 32 + i] = -a * sn + b * cs;
    }
}

// ---------------------------------------------------------------------------
// GEMM core: computes a 128x128 tile of A @ B^T into acc.
// Double-buffered smem + register prefetch, one __syncthreads per K-slab.
// ---------------------------------------------------------------------------
#define GBM 128
#define GBN 128
#define GBK 16
#define LDS 132   // 128 + 4 pad

struct GemmSmem {
    float As[2][GBK * LDS];
    float Bs[2][GBK * LDS];
};

__device__ __forceinline__ void gemm_core(
    GemmSmem& sm, const float* __restrict__ Ag, const float* __restrict__ Bg,
    int K, float acc[8][8], int tid, int tx, int ty)
{
    int lr[2], lc[2];
    #pragma unroll
    for (int tctr = 0; tctr < 2; tctr++) {
        int f = tid + tctr * 256;      // 0..511
        lr[tctr] = f >> 2;             // tile row 0..127
        lc[tctr] = (f & 3) * 4;        // k sub-offset 0/4/8/12
    }

    float4 pva[2], pvb[2];
    #pragma unroll
    for (int tctr = 0; tctr < 2; tctr++) {
        pva[tctr] = *reinterpret_cast<const float4*>(Ag + (size_t)lr[tctr] * K + lc[tctr]);
        pvb[tctr] = *reinterpret_cast<const float4*>(Bg + (size_t)lr[tctr] * K + lc[tctr]);
    }
    #pragma unroll
    for (int tctr = 0; tctr < 2; tctr++) {
        int r = lr[tctr], c4 = lc[tctr];
        sm.As[0][(c4 + 0) * LDS + r] = pva[tctr].x;
        sm.As[0][(c4 + 1) * LDS + r] = pva[tctr].y;
        sm.As[0][(c4 + 2) * LDS + r] = pva[tctr].z;
        sm.As[0][(c4 + 3) * LDS + r] = pva[tctr].w;
        sm.Bs[0][(c4 + 0) * LDS + r] = pvb[tctr].x;
        sm.Bs[0][(c4 + 1) * LDS + r] = pvb[tctr].y;
        sm.Bs[0][(c4 + 2) * LDS + r] = pvb[tctr].z;
        sm.Bs[0][(c4 + 3) * LDS + r] = pvb[tctr].w;
    }
    __syncthreads();

    const int nslab = K / GBK;
    for (int s = 0; s < nslab; s++) {
        const int cur = s & 1;
        const bool have_next = (s + 1) < nslab;

        if (have_next) {
            const int kn = (s + 1) * GBK;
            #pragma unroll
            for (int tctr = 0; tctr < 2; tctr++) {
                pva[tctr] = *reinterpret_cast<const float4*>(Ag + (size_t)lr[tctr] * K + kn + lc[tctr]);
                pvb[tctr] = *reinterpret_cast<const float4*>(Bg + (size_t)lr[tctr] * K + kn + lc[tctr]);
            }
        }

        #pragma unroll
        for (int kk = 0; kk < GBK; kk++) {
            float4 a0 = *reinterpret_cast<const float4*>(&sm.As[cur][kk * LDS + ty * 8]);
            float4 a1 = *reinterpret_cast<const float4*>(&sm.As[cur][kk * LDS + ty * 8 + 4]);
            float4 b0 = *reinterpret_cast<const float4*>(&sm.Bs[cur][kk * LDS + tx * 8]);
            float4 b1 = *reinterpret_cast<const float4*>(&sm.Bs[cur][kk * LDS + tx * 8 + 4]);
            float a[8] = {a0.x, a0.y, a0.z, a0.w, a1.x, a1.y, a1.z, a1.w};
            float b[8] = {b0.x, b0.y, b0.z, b0.w, b1.x, b1.y, b1.z, b1.w};
            #pragma unroll
            for (int i = 0; i < 8; i++)
                #pragma unroll
                for (int j = 0; j < 8; j++)
                    acc[i][j] += a[i] * b[j];
        }

        if (have_next) {
            const int nxt = cur ^ 1;
            #pragma unroll
            for (int tctr = 0; tctr < 2; tctr++) {
                int r = lr[tctr], c4 = lc[tctr];
                sm.As[nxt][(c4 + 0) * LDS + r] = pva[tctr].x;
                sm.As[nxt][(c4 + 1) * LDS + r] = pva[tctr].y;
                sm.As[nxt][(c4 + 2) * LDS + r] = pva[tctr].z;
                sm.As[nxt][(c4 + 3) * LDS + r] = pva[tctr].w;
                sm.Bs[nxt][(c4 + 0) * LDS + r] = pvb[tctr].x;
                sm.Bs[nxt][(c4 + 1) * LDS + r] = pvb[tctr].y;
                sm.Bs[nxt][(c4 + 2) * LDS + r] = pvb[tctr].z;
                sm.Bs[nxt][(c4 + 3) * LDS + r] = pvb[tctr].w;
            }
        }
        __syncthreads();
    }
}

// ---------------------------------------------------------------------------
// Standard NT GEMM with epilogue.
// EPI: 0 = store, 1 = *mul, 2 = +res, 3 = +res +bias
// ---------------------------------------------------------------------------
template<int EPI>
__global__ __launch_bounds__(256, 2) void gemm_nt(
    const float* __restrict__ A, const float* __restrict__ B, float* __restrict__ C,
    int M, int N, int K,
    const float* __restrict__ res, const float* __restrict__ mul,
    const float* __restrict__ bias)
{
    __shared__ GemmSmem sm;
    const int tid = threadIdx.x;
    const int tx = tid & 15;
    const int ty = tid >> 4;
    const int row0 = blockIdx.y * GBM;
    const int col0 = blockIdx.x * GBN;

    float acc[8][8] = {};
    gemm_core(sm, A + (size_t)row0 * K, B + (size_t)col0 * K, K, acc, tid, tx, ty);

    #pragma unroll
    for (int i = 0; i < 8; i++) {
        const size_t r = row0 + ty * 8 + i;
        const size_t cbase = (size_t)col0 + tx * 8;
        float4 v0 = make_float4(acc[i][0], acc[i][1], acc[i][2], acc[i][3]);
        float4 v1 = make_float4(acc[i][4], acc[i][5], acc[i][6], acc[i][7]);
        if (EPI == 1) {
            float4 m0 = *reinterpret_cast<const float4*>(mul + r * N + cbase);
            float4 m1 = *reinterpret_cast<const float4*>(mul + r * N + cbase + 4);
            v0.x *= m0.x; v0.y *= m0.y; v0.z *= m0.z; v0.w *= m0.w;
            v1.x *= m1.x; v1.y *= m1.y; v1.z *= m1.z; v1.w *= m1.w;
        }
        if (EPI == 2 || EPI == 3) {
            float4 r0 = *reinterpret_cast<const float4*>(res + r * N + cbase);
            float4 r1 = *reinterpret_cast<const float4*>(res + r * N + cbase + 4);
            v0.x += r0.x; v0.y += r0.y; v0.z += r0.z; v0.w += r0.w;
            v1.x += r1.x; v1.y += r1.y; v1.z += r1.z; v1.w += r1.w;
        }
        if (EPI == 3) {
            float4 b0 = *reinterpret_cast<const float4*>(bias + cbase);
            float4 b1 = *reinterpret_cast<const float4*>(bias + cbase + 4);
            v0.x += b0.x; v0.y += b0.y; v0.z += b0.z; v0.w += b0.w;
            v1.x += b1.x; v1.y += b1.y; v1.z += b1.z; v1.w += b1.w;
        }
        *reinterpret_cast<float4*>(C + r * N + cbase)     = v0;
        *reinterpret_cast<float4*>(C + r * N + cbase + 4) = v1;
    }
}

// ---------------------------------------------------------------------------
// Fused 5-way projection GEMM: blockIdx.z selects (weight, output) pair.
// All 5 share A = h.  grid = (6, 16, 5) = 480 CTAs -> fills the chip.
// ---------------------------------------------------------------------------
__global__ __launch_bounds__(256, 2) void gemm_proj5(
    const float* __restrict__ A,
    const float* __restrict__ W0, const float* __restrict__ W1,
    const float* __restrict__ W2, const float* __restrict__ W3,
    const float* __restrict__ W4,
    float* __restrict__ C0, float* __restrict__ C1,
    float* __restrict__ C2, float* __restrict__ C3,
    float* __restrict__ C4)
{
    __shared__ GemmSmem sm;
    const int tid = threadIdx.x;
    const int tx = tid & 15;
    const int ty = tid >> 4;
    const int row0 = blockIdx.y * GBM;
    const int col0 = blockIdx.x * GBN;
    const int K = C_DIM, N = C_DIM;

    const float* B;
    float* C;
    switch (blockIdx.z) {
        case 0: B = W0; C = C0; break;
        case 1: B = W1; C = C1; break;
        case 2: B = W2; C = C2; break;
        case 3: B = W3; C = C3; break;
        default: B = W4; C = C4; break;
    }

    float acc[8][8] = {};
    gemm_core(sm, A + (size_t)row0 * K, B + (size_t)col0 * K, K, acc, tid, tx, ty);

    #pragma unroll
    for (int i = 0; i < 8; i++) {
        const size_t r = row0 + ty * 8 + i;
        const size_t cbase = (size_t)col0 + tx * 8;
        float4 v0 = make_float4(acc[i][0], acc[i][1], acc[i][2], acc[i][3]);
        float4 v1 = make_float4(acc[i][4], acc[i][5], acc[i][6], acc[i][7]);
        *reinterpret_cast<float4*>(C + r * N + cbase)     = v0;
        *reinterpret_cast<float4*>(C + r * N + cbase + 4) = v1;
    }
}

// ---------------------------------------------------------------------------
// Fused causal "pattern" attention:
//   P = tril( (Q·K^T / 64) * (Q2·K2^T / 64) ),  Z = P @ V
// grid = (T/64, H), 256 threads, 64-row q tile, 64-row k tiles.
// ---------------------------------------------------------------------------
#define ALD 68                    // 64 + 4 pad
#define ATTN_SMEM (5 * 64 * ALD * (int)sizeof(float))

__global__ __launch_bounds__(256, 2) void attn_kernel(
    const float* __restrict__ q, const float* __restrict__ k,
    const float* __restrict__ q2, const float* __restrict__ k2,
    const float* __restrict__ v, float* __restrict__ z)
{
    extern __shared__ float sm[];
    float* Qs  = sm;
    float* Q2s = Qs  + 64 * ALD;
    float* Ks  = Q2s + 64 * ALD;   // reused for the V tile
    float* K2s = Ks  + 64 * ALD;
    float* Ps  = K2s + 64 * ALD;

    const int head = blockIdx.y;
    const int q0   = blockIdx.x * 64;
    const int tid  = threadIdx.x;
    const int tx   = tid & 15;
    const int ty   = tid >> 4;
    const size_t hb = (size_t)head * D_HEAD;

    // load persistent Q tiles
    for (int f = tid; f < 64 * 16; f += 256) {
        int r  = f >> 4;
        int c4 = (f & 15) * 4;
        *reinterpret_cast<float4*>(&Qs [r * ALD + c4]) =
            *reinterpret_cast<const float4*>(&q [(size_t)(q0 + r) * C_DIM + hb + c4]);
        *reinterpret_cast<float4*>(&Q2s[r * ALD + c4]) =
            *reinterpret_cast<const float4*>(&q2[(size_t)(q0 + r) * C_DIM + hb + c4]);
    }

    float zacc[4][4] = {};

    for (int j0 = 0; j0 <= q0; j0 += 64) {
        __syncthreads();   // protect Ks/Ps from previous iteration's readers + Q loads on iter 0
        for (int f = tid; f < 64 * 16; f += 256) {
            int r  = f >> 4;
            int c4 = (f & 15) * 4;
            *reinterpret_cast<float4*>(&Ks [r * ALD + c4]) =
                *reinterpret_cast<const float4*>(&k [(size_t)(j0 + r) * C_DIM + hb + c4]);
            *reinterpret_cast<float4*>(&K2s[r * ALD + c4]) =
                *reinterpret_cast<const float4*>(&k2[(size_t)(j0 + r) * C_DIM + hb + c4]);
        }
        __syncthreads();

        float s1[4][4] = {}, s2[4][4] = {};
        #pragma unroll 4
        for (int d = 0; d < 64; d += 4) {
            float4 a1[4], a2[4], b1[4], b2[4];
            #pragma unroll
            for (int u = 0; u < 4; u++) {
                a1[u] = *reinterpret_cast<const float4*>(&Qs [(ty * 4 + u) * ALD + d]);
                a2[u] = *reinterpret_cast<const float4*>(&Q2s[(ty * 4 + u) * ALD + d]);
                b1[u] = *reinterpret_cast<const float4*>(&Ks [(tx * 4 + u) * ALD + d]);
                b2[u] = *reinterpret_cast<const float4*>(&K2s[(tx * 4 + u) * ALD + d]);
            }
            #pragma unroll
            for (int ii = 0; ii < 4; ii++)
                #pragma unroll
                for (int jj = 0; jj < 4; jj++) {
                    s1[ii][jj] += a1[ii].x * b1[jj].x + a1[ii].y * b1[jj].y
                                + a1[ii].z * b1[jj].z + a1[ii].w * b1[jj].w;
                    s2[ii][jj] += a2[ii].x * b2[jj].x + a2[ii].y * b2[jj].y
                                + a2[ii].z * b2[jj].z + a2[ii].w * b2[jj].w;
                }
        }

        // masked, scaled pattern into smem
        #pragma unroll
        for (int ii = 0; ii < 4; ii++)
            #pragma unroll
            for (int jj = 0; jj < 4; jj++) {
                int gi = q0 + ty * 4 + ii;
                int gj = j0 + tx * 4 + jj;
                Ps[(ty * 4 + ii) * ALD + tx * 4 + jj] =
                    (gj <= gi) ? s1[ii][jj] * s2[ii][jj] * (1.0f / 4096.0f) : 0.0f;
            }
        __syncthreads();

        // load V over Ks
        for (int f = tid; f < 64 * 16; f += 256) {
            int r  = f >> 4;
            int c4 = (f & 15) * 4;
            *reinterpret_cast<float4*>(&Ks[r * ALD + c4]) =
                *reinterpret_cast<const float4*>(&v[(size_t)(j0 + r) * C_DIM + hb + c4]);
        }
        __syncthreads();

        // Z += P @ V
        #pragma unroll 4
        for (int j = 0; j < 64; j += 4) {
            float4 pa[4];
            float  vb[4][4];
            #pragma unroll
            for (int u = 0; u < 4; u++) {
                pa[u] = *reinterpret_cast<const float4*>(&Ps[(ty * 4 + u) * ALD + j]);
                float4 t = *reinterpret_cast<const float4*>(&Ks[(j + u) * ALD + tx * 4]);
                vb[u][0] = t.x; vb[u][1] = t.y; vb[u][2] = t.z; vb[u][3] = t.w;
            }
            #pragma unroll
            for (int ii = 0; ii < 4; ii++) {
                #pragma unroll
                for (int dd = 0; dd < 4; dd++) {
                    zacc[ii][dd] += pa[ii].x * vb[0][dd] + pa[ii].y * vb[1][dd]
                                  + pa[ii].z * vb[2][dd] + pa[ii].w * vb[3][dd];
                }
            }
        }
    }

    #pragma unroll
    for (int ii = 0; ii < 4; ii++) {
        float4 o = make_float4(zacc[ii][0], zacc[ii][1], zacc[ii][2], zacc[ii][3]);
        *reinterpret_cast<float4*>(
            &z[(size_t)(q0 + ty * 4 + ii) * C_DIM + hb + tx * 4]) = o;
    }
}

// ---------------------------------------------------------------------------
// Host orchestration
// ---------------------------------------------------------------------------
extern "C" void kernel_launch(void* const* d_in, const int* in_sizes, int n_in,
                              void* d_out, int out_size)
{
    const float* x   = (const float*)d_in[0];
    const float* Wq  = (const float*)d_in[1];
    const float* Wk  = (const float*)d_in[2];
    const float* Wq2 = (const float*)d_in[3];
    const float* Wk2 = (const float*)d_in[4];
    const float* Wv  = (const float*)d_in[5];
    const float* Wo  = (const float*)d_in[6];
    const float* Wp1 = (const float*)d_in[7];
    const float* Wp2 = (const float*)d_in[8];
    const float* Wd  = (const float*)d_in[9];
    const float* bd  = (const float*)d_in[10];
    float* out = (float*)d_out;

    float *h, *q, *k, *q2, *k2, *v, *z, *x1, *h2, *t1, *hid;
    cudaGetSymbolAddress((void**)&h,   g_h);
    cudaGetSymbolAddress((void**)&q,   g_q);
    cudaGetSymbolAddress((void**)&k,   g_k);
    cudaGetSymbolAddress((void**)&q2,  g_q2);
    cudaGetSymbolAddress((void**)&k2,  g_k2);
    cudaGetSymbolAddress((void**)&v,   g_v);
    cudaGetSymbolAddress((void**)&z,   g_z);
    cudaGetSymbolAddress((void**)&x1,  g_x1);
    cudaGetSymbolAddress((void**)&h2,  g_h2);
    cudaGetSymbolAddress((void**)&t1,  g_t1);
    cudaGetSymbolAddress((void**)&hid, g_hid);

    // 1. h = rms(x)
    rms_kernel<<<T_SEQ, 256>>>(x, h);

    // 2. fused projections (one launch, 480 CTAs)
    dim3 gp5(C_DIM / GBN, T_SEQ / GBM, 5);
    gemm_proj5<<<gp5, 256>>>(h, Wq, Wk, Wq2, Wk2, Wv, q, k, q2, k2, v);

    // 3. RoPE
    rope_kernel<<<T_SEQ, N_HEAD * 32>>>(q, k, q2, k2);

    // 4. fused attention -> z
    cudaFuncSetAttribute(attn_kernel, cudaFuncAttributeMaxDynamicSharedMemorySize, ATTN_SMEM);
    attn_kernel<<<dim3(T_SEQ / 64, N_HEAD), 256, ATTN_SMEM>>>(q, k, q2, k2, v, z);

    // 5. x1 = x + z @ Wo^T
    dim3 gp(C_DIM / GBN, T_SEQ / GBM);
    gemm_nt<2><<<gp, 256>>>(z, Wo, x1, T_SEQ, C_DIM, C_DIM, x, nullptr, nullptr);

    // 6. h2 = rms(x1)
    rms_kernel<<<T_SEQ, 256>>>(x1, h2);

    // 7. MLP: t1 = h2@Wp1^T ; hid = (h2@Wp2^T) * t1
    dim3 gm(D_HID / GBN, T_SEQ / GBM);
    gemm_nt<0><<<gm, 256>>>(h2, Wp1, t1,  T_SEQ, D_HID, C_DIM, nullptr, nullptr, nullptr);
    gemm_nt<1><<<gm, 256>>>(h2, Wp2, hid, T_SEQ, D_HID, C_DIM, nullptr, t1, nullptr);

    // 8. out = x1 + hid @ Wd^T + bd
    gemm_nt<3><<<gp, 256>>>(hid, Wd, out, T_SEQ, C_DIM, D_HID, x1, nullptr, bd);
}

// round 6
// speedup vs baseline: 1.2519x; 1.2519x over previous
#include <cuda_runtime.h>
#include <cuda_bf16.h>
#include <cstddef>

// Problem constants
#define T_SEQ 2048
#define C_DIM 768
#define N_HEAD 12
#define D_HEAD 64
#define D_HID 3072

// ---------------------------------------------------------------------------
// Scratch (no cudaMalloc allowed)
// ---------------------------------------------------------------------------
__device__ float g_h  [T_SEQ * C_DIM];
__device__ float g_q  [T_SEQ * C_DIM];
__device__ float g_k  [T_SEQ * C_DIM];
__device__ float g_q2 [T_SEQ * C_DIM];
__device__ float g_k2 [T_SEQ * C_DIM];
__device__ float g_v  [T_SEQ * C_DIM];
__device__ float g_z  [T_SEQ * C_DIM];
__device__ float g_x1 [T_SEQ * C_DIM];
__device__ float g_h2 [T_SEQ * C_DIM];
__device__ float g_t1 [T_SEQ * D_HID];
__device__ float g_hid[T_SEQ * D_HID];

// ---------------------------------------------------------------------------
// RMSNorm: one block per token
// ---------------------------------------------------------------------------
__global__ void rms_kernel(const float* __restrict__ x, float* __restrict__ o)
{
    const int t = blockIdx.x;
    const float* xr = x + (size_t)t * C_DIM;
    float s = 0.f;
    for (int i = threadIdx.x; i < C_DIM; i += 256) {
        float v = xr[i];
        s += v * v;
    }
    #pragma unroll
    for (int off = 16; off; off >>= 1)
        s += __shfl_down_sync(0xffffffffu, s, off);
    __shared__ float ws[8];
    __shared__ float scale_s;
    if ((threadIdx.x & 31) == 0) ws[threadIdx.x >> 5] = s;
    __syncthreads();
    if (threadIdx.x == 0) {
        float tot = 0.f;
        #pragma unroll
        for (int w = 0; w < 8; w++) tot += ws[w];
        scale_s = rsqrtf(tot * (1.0f / C_DIM) + 1e-6f);
    }
    __syncthreads();
    const float sc = scale_s;
    for (int i = threadIdx.x; i < C_DIM; i += 256)
        o[(size_t)t * C_DIM + i] = xr[i] * sc;
}

// ---------------------------------------------------------------------------
// RoPE in-place on q,k,q2,k2.  grid = T, block = H*32 = 384
// ---------------------------------------------------------------------------
__global__ void rope_kernel(float* __restrict__ q, float* __restrict__ k,
                            float* __restrict__ q2, float* __restrict__ k2)
{
    const int t = blockIdx.x;
    const int p = threadIdx.x;        // 0..383
    const int h = p >> 5;
    const int i = p & 31;
    const float inv = expf(-(float)i * (9.210340371976184f / 32.0f));
    const float ang = (float)t * inv;
    float sn, cs;
    sincosf(ang, &sn, &cs);
    const size_t base = (size_t)t * C_DIM + h * D_HEAD;
    {
        float a = q[base + i], b = q[base + 32 + i];
        q[base + i]      = a * cs + b * sn;
        q[base + 32 + i] = -a * sn + b * cs;
    }
    {
        float a = k[base + i], b = k[base + 32 + i];
        k[base + i]      = a * cs + b * sn;
        k[base + 32 + i] = -a * sn + b * cs;
    }
    {
        float a = q2[base + i], b = q2[base + 32 + i];
        q2[base + i]      = a * cs + b * sn;
        q2[base + 32 + i] = -a * sn + b * cs;
    }
    {
        float a = k2[base + i], b = k2[base + 32 + i];
        k2[base + i]      = a * cs + b * sn;
        k2[base + 32 + i] = -a * sn + b * cs;
    }
}

// ---------------------------------------------------------------------------
// GEMM core: computes a 128x128 tile of A @ B^T into acc.
// Double-buffered smem + register prefetch, one __syncthreads per K-slab.
// ---------------------------------------------------------------------------
#define GBM 128
#define GBN 128
#define GBK 16
#define LDS 132   // 128 + 4 pad

struct GemmSmem {
    float As[2][GBK * LDS];
    float Bs[2][GBK * LDS];
};

__device__ __forceinline__ void gemm_core(
    GemmSmem& sm, const float* __restrict__ Ag, const float* __restrict__ Bg,
    int K, float acc[8][8], int tid, int tx, int ty)
{
    int lr[2], lc[2];
    #pragma unroll
    for (int tctr = 0; tctr < 2; tctr++) {
        int f = tid + tctr * 256;      // 0..511
        lr[tctr] = f >> 2;             // tile row 0..127
        lc[tctr] = (f & 3) * 4;        // k sub-offset 0/4/8/12
    }

    float4 pva[2], pvb[2];
    #pragma unroll
    for (int tctr = 0; tctr < 2; tctr++) {
        pva[tctr] = *reinterpret_cast<const float4*>(Ag + (size_t)lr[tctr] * K + lc[tctr]);
        pvb[tctr] = *reinterpret_cast<const float4*>(Bg + (size_t)lr[tctr] * K + lc[tctr]);
    }
    #pragma unroll
    for (int tctr = 0; tctr < 2; tctr++) {
        int r = lr[tctr], c4 = lc[tctr];
        sm.As[0][(c4 + 0) * LDS + r] = pva[tctr].x;
        sm.As[0][(c4 + 1) * LDS + r] = pva[tctr].y;
        sm.As[0][(c4 + 2) * LDS + r] = pva[tctr].z;
        sm.As[0][(c4 + 3) * LDS + r] = pva[tctr].w;
        sm.Bs[0][(c4 + 0) * LDS + r] = pvb[tctr].x;
        sm.Bs[0][(c4 + 1) * LDS + r] = pvb[tctr].y;
        sm.Bs[0][(c4 + 2) * LDS + r] = pvb[tctr].z;
        sm.Bs[0][(c4 + 3) * LDS + r] = pvb[tctr].w;
    }
    __syncthreads();

    const int nslab = K / GBK;
    for (int s = 0; s < nslab; s++) {
        const int cur = s & 1;
        const bool have_next = (s + 1) < nslab;

        if (have_next) {
            const int kn = (s + 1) * GBK;
            #pragma unroll
            for (int tctr = 0; tctr < 2; tctr++) {
                pva[tctr] = *reinterpret_cast<const float4*>(Ag + (size_t)lr[tctr] * K + kn + lc[tctr]);
                pvb[tctr] = *reinterpret_cast<const float4*>(Bg + (size_t)lr[tctr] * K + kn + lc[tctr]);
            }
        }

        #pragma unroll
        for (int kk = 0; kk < GBK; kk++) {
            float4 a0 = *reinterpret_cast<const float4*>(&sm.As[cur][kk * LDS + ty * 8]);
            float4 a1 = *reinterpret_cast<const float4*>(&sm.As[cur][kk * LDS + ty * 8 + 4]);
            float4 b0 = *reinterpret_cast<const float4*>(&sm.Bs[cur][kk * LDS + tx * 8]);
            float4 b1 = *reinterpret_cast<const float4*>(&sm.Bs[cur][kk * LDS + tx * 8 + 4]);
            float a[8] = {a0.x, a0.y, a0.z, a0.w, a1.x, a1.y, a1.z, a1.w};
            float b[8] = {b0.x, b0.y, b0.z, b0.w, b1.x, b1.y, b1.z, b1.w};
            #pragma unroll
            for (int i = 0; i < 8; i++)
                #pragma unroll
                for (int j = 0; j < 8; j++)
                    acc[i][j] += a[i] * b[j];
        }

        if (have_next) {
            const int nxt = cur ^ 1;
            #pragma unroll
            for (int tctr = 0; tctr < 2; tctr++) {
                int r = lr[tctr], c4 = lc[tctr];
                sm.As[nxt][(c4 + 0) * LDS + r] = pva[tctr].x;
                sm.As[nxt][(c4 + 1) * LDS + r] = pva[tctr].y;
                sm.As[nxt][(c4 + 2) * LDS + r] = pva[tctr].z;
                sm.As[nxt][(c4 + 3) * LDS + r] = pva[tctr].w;
                sm.Bs[nxt][(c4 + 0) * LDS + r] = pvb[tctr].x;
                sm.Bs[nxt][(c4 + 1) * LDS + r] = pvb[tctr].y;
                sm.Bs[nxt][(c4 + 2) * LDS + r] = pvb[tctr].z;
                sm.Bs[nxt][(c4 + 3) * LDS + r] = pvb[tctr].w;
            }
        }
        __syncthreads();
    }
}

// ---------------------------------------------------------------------------
// Standard NT GEMM with epilogue.
// EPI: 0 = store, 1 = *mul, 2 = +res, 3 = +res +bias
// ---------------------------------------------------------------------------
template<int EPI>
__global__ __launch_bounds__(256, 2) void gemm_nt(
    const float* __restrict__ A, const float* __restrict__ B, float* __restrict__ C,
    int M, int N, int K,
    const float* __restrict__ res, const float* __restrict__ mul,
    const float* __restrict__ bias)
{
    __shared__ GemmSmem sm;
    const int tid = threadIdx.x;
    const int tx = tid & 15;
    const int ty = tid >> 4;
    const int row0 = blockIdx.y * GBM;
    const int col0 = blockIdx.x * GBN;

    float acc[8][8] = {};
    gemm_core(sm, A + (size_t)row0 * K, B + (size_t)col0 * K, K, acc, tid, tx, ty);

    #pragma unroll
    for (int i = 0; i < 8; i++) {
        const size_t r = row0 + ty * 8 + i;
        const size_t cbase = (size_t)col0 + tx * 8;
        float4 v0 = make_float4(acc[i][0], acc[i][1], acc[i][2], acc[i][3]);
        float4 v1 = make_float4(acc[i][4], acc[i][5], acc[i][6], acc[i][7]);
        if (EPI == 1) {
            float4 m0 = *reinterpret_cast<const float4*>(mul + r * N + cbase);
            float4 m1 = *reinterpret_cast<const float4*>(mul + r * N + cbase + 4);
            v0.x *= m0.x; v0.y *= m0.y; v0.z *= m0.z; v0.w *= m0.w;
            v1.x *= m1.x; v1.y *= m1.y; v1.z *= m1.z; v1.w *= m1.w;
        }
        if (EPI == 2 || EPI == 3) {
            float4 r0 = *reinterpret_cast<const float4*>(res + r * N + cbase);
            float4 r1 = *reinterpret_cast<const float4*>(res + r * N + cbase + 4);
            v0.x += r0.x; v0.y += r0.y; v0.z += r0.z; v0.w += r0.w;
            v1.x += r1.x; v1.y += r1.y; v1.z += r1.z; v1.w += r1.w;
        }
        if (EPI == 3) {
            float4 b0 = *reinterpret_cast<const float4*>(bias + cbase);
            float4 b1 = *reinterpret_cast<const float4*>(bias + cbase + 4);
            v0.x += b0.x; v0.y += b0.y; v0.z += b0.z; v0.w += b0.w;
            v1.x += b1.x; v1.y += b1.y; v1.z += b1.z; v1.w += b1.w;
        }
        *reinterpret_cast<float4*>(C + r * N + cbase)     = v0;
        *reinterpret_cast<float4*>(C + r * N + cbase + 4) = v1;
    }
}

// ---------------------------------------------------------------------------
// Fused 5-way projection GEMM: blockIdx.z selects (weight, output) pair.
// ---------------------------------------------------------------------------
__global__ __launch_bounds__(256, 2) void gemm_proj5(
    const float* __restrict__ A,
    const float* __restrict__ W0, const float* __restrict__ W1,
    const float* __restrict__ W2, const float* __restrict__ W3,
    const float* __restrict__ W4,
    float* __restrict__ C0, float* __restrict__ C1,
    float* __restrict__ C2, float* __restrict__ C3,
    float* __restrict__ C4)
{
    __shared__ GemmSmem sm;
    const int tid = threadIdx.x;
    const int tx = tid & 15;
    const int ty = tid >> 4;
    const int row0 = blockIdx.y * GBM;
    const int col0 = blockIdx.x * GBN;
    const int K = C_DIM, N = C_DIM;

    const float* B;
    float* C;
    switch (blockIdx.z) {
        case 0: B = W0; C = C0; break;
        case 1: B = W1; C = C1; break;
        case 2: B = W2; C = C2; break;
        case 3: B = W3; C = C3; break;
        default: B = W4; C = C4; break;
    }

    float acc[8][8] = {};
    gemm_core(sm, A + (size_t)row0 * K, B + (size_t)col0 * K, K, acc, tid, tx, ty);

    #pragma unroll
    for (int i = 0; i < 8; i++) {
        const size_t r = row0 + ty * 8 + i;
        const size_t cbase = (size_t)col0 + tx * 8;
        float4 v0 = make_float4(acc[i][0], acc[i][1], acc[i][2], acc[i][3]);
        float4 v1 = make_float4(acc[i][4], acc[i][5], acc[i][6], acc[i][7]);
        *reinterpret_cast<float4*>(C + r * N + cbase)     = v0;
        *reinterpret_cast<float4*>(C + r * N + cbase + 4) = v1;
    }
}

// ---------------------------------------------------------------------------
// Fused causal "pattern" attention:
//   P = tril( (Q·K^T / 64) * (Q2·K2^T / 64) ),  Z = P @ V
// 128-row q tile per CTA, 256 threads as 16x16, 8x4 micro-tile.
// K/K2 stored TRANSPOSED in smem ([d][row]) -> conflict-free b-loads.
// grid = (T/128, H), 1 CTA/SM (153 KB smem). Longest tiles first.
// ---------------------------------------------------------------------------
#define ALD 68                    // 64 + 4 pad (for 64-wide rows)
#define ATTN_SMEM ((3 * 128 + 3 * 64) * ALD * (int)sizeof(float))

__global__ __launch_bounds__(256, 1) void attn_kernel(
    const float* __restrict__ q, const float* __restrict__ k,
    const float* __restrict__ q2, const float* __restrict__ k2,
    const float* __restrict__ v, float* __restrict__ z)
{
    extern __shared__ float sm[];
    float* Qs  = sm;                     // [128][ALD] row-major (row, d)
    float* Q2s = Qs  + 128 * ALD;        // [128][ALD]
    float* K1T = Q2s + 128 * ALD;        // [64][ALD]  TRANSPOSED: (d, row)
    float* K2T = K1T + 64 * ALD;         // [64][ALD]  TRANSPOSED
    float* Vs  = K2T + 64 * ALD;         // [64][ALD]  row-major (row, d)
    float* Ps  = Vs  + 64 * ALD;         // [128][ALD]

    const int head = blockIdx.y;
    const int q0   = (gridDim.x - 1 - blockIdx.x) * 128;   // long tiles first
    const int tid  = threadIdx.x;
    const int tx   = tid & 15;           // col group: 4 k-cols
    const int ty   = tid >> 4;           // row group: 8 q-rows
    const size_t hb = (size_t)head * D_HEAD;

    // load persistent Q tiles (128 rows)
    for (int f = tid; f < 128 * 16; f += 256) {
        int r  = f >> 4;
        int c4 = (f & 15) * 4;
        *reinterpret_cast<float4*>(&Qs [r * ALD + c4]) =
            *reinterpret_cast<const float4*>(&q [(size_t)(q0 + r) * C_DIM + hb + c4]);
        *reinterpret_cast<float4*>(&Q2s[r * ALD + c4]) =
            *reinterpret_cast<const float4*>(&q2[(size_t)(q0 + r) * C_DIM + hb + c4]);
    }

    float zacc[8][4] = {};

    for (int j0 = 0; j0 <= q0 + 64; j0 += 64) {
        // barrier 1: previous iteration's readers done (and Q stores on iter 0)
        __syncthreads();

        // single load phase: K,K2 transposed (scalar stores), V row-major
        for (int f = tid; f < 64 * 16; f += 256) {
            int r  = f >> 4;
            int c4 = (f & 15) * 4;
            const size_t rowb = (size_t)(j0 + r) * C_DIM + hb + c4;
            float4 kv = *reinterpret_cast<const float4*>(&k [rowb]);
            K1T[(c4 + 0) * ALD + r] = kv.x;
            K1T[(c4 + 1) * ALD + r] = kv.y;
            K1T[(c4 + 2) * ALD + r] = kv.z;
            K1T[(c4 + 3) * ALD + r] = kv.w;
            float4 k2v = *reinterpret_cast<const float4*>(&k2[rowb]);
            K2T[(c4 + 0) * ALD + r] = k2v.x;
            K2T[(c4 + 1) * ALD + r] = k2v.y;
            K2T[(c4 + 2) * ALD + r] = k2v.z;
            K2T[(c4 + 3) * ALD + r] = k2v.w;
            *reinterpret_cast<float4*>(&Vs[r * ALD + c4]) =
                *reinterpret_cast<const float4*>(&v[rowb]);
        }
        // barrier 2: tiles visible
        __syncthreads();

        float s1[8][4] = {}, s2[8][4] = {};
        #pragma unroll 4
        for (int d = 0; d < 64; d += 4) {
            // b fragments: 4 k-cols x 4 d, conflict-free (lane-consecutive)
            float kb1[4][4], kb2[4][4];
            #pragma unroll
            for (int u = 0; u < 4; u++) {
                float4 t1 = *reinterpret_cast<const float4*>(&K1T[(d + u) * ALD + tx * 4]);
                kb1[u][0] = t1.x; kb1[u][1] = t1.y; kb1[u][2] = t1.z; kb1[u][3] = t1.w;
                float4 t2 = *reinterpret_cast<const float4*>(&K2T[(d + u) * ALD + tx * 4]);
                kb2[u][0] = t2.x; kb2[u][1] = t2.y; kb2[u][2] = t2.z; kb2[u][3] = t2.w;
            }
            #pragma unroll
            for (int ii = 0; ii < 8; ii++) {
                float4 A1 = *reinterpret_cast<const float4*>(&Qs [(ty * 8 + ii) * ALD + d]);
                float4 A2 = *reinterpret_cast<const float4*>(&Q2s[(ty * 8 + ii) * ALD + d]);
                float a1f[4] = {A1.x, A1.y, A1.z, A1.w};
                float a2f[4] = {A2.x, A2.y, A2.z, A2.w};
                #pragma unroll
                for (int jj = 0; jj < 4; jj++) {
                    #pragma unroll
                    for (int dd = 0; dd < 4; dd++) {
                        s1[ii][jj] += a1f[dd] * kb1[dd][jj];
                        s2[ii][jj] += a2f[dd] * kb2[dd][jj];
                    }
                }
            }
        }

        // masked, scaled pattern into smem (vector store, conflict-free)
        #pragma unroll
        for (int ii = 0; ii < 8; ii++) {
            const int gi = q0 + ty * 8 + ii;
            float p[4];
            #pragma unroll
            for (int jj = 0; jj < 4; jj++) {
                const int gj = j0 + tx * 4 + jj;
                p[jj] = (gj <= gi) ? s1[ii][jj] * s2[ii][jj] * (1.0f / 4096.0f) : 0.0f;
            }
            *reinterpret_cast<float4*>(&Ps[(ty * 8 + ii) * ALD + tx * 4]) =
                make_float4(p[0], p[1], p[2], p[3]);
        }
        // barrier 3: P complete
        __syncthreads();

        // Z += P @ V   (8 rows x 4 d-cols per thread)
        #pragma unroll 4
        for (int j = 0; j < 64; j += 4) {
            float vbf[4][4];
            #pragma unroll
            for (int u = 0; u < 4; u++) {
                float4 t = *reinterpret_cast<const float4*>(&Vs[(j + u) * ALD + tx * 4]);
                vbf[u][0] = t.x; vbf[u][1] = t.y; vbf[u][2] = t.z; vbf[u][3] = t.w;
            }
            #pragma unroll
            for (int ii = 0; ii < 8; ii++) {
                float4 pa = *reinterpret_cast<const float4*>(&Ps[(ty * 8 + ii) * ALD + j]);
                float paf[4] = {pa.x, pa.y, pa.z, pa.w};
                #pragma unroll
                for (int dd = 0; dd < 4; dd++) {
                    zacc[ii][dd] += paf[0] * vbf[0][dd] + paf[1] * vbf[1][dd]
                                  + paf[2] * vbf[2][dd] + paf[3] * vbf[3][dd];
                }
            }
        }
    }

    #pragma unroll
    for (int ii = 0; ii < 8; ii++) {
        float4 o = make_float4(zacc[ii][0], zacc[ii][1], zacc[ii][2], zacc[ii][3]);
        *reinterpret_cast<float4*>(
            &z[(size_t)(q0 + ty * 8 + ii) * C_DIM + hb + tx * 4]) = o;
    }
}

// ---------------------------------------------------------------------------
// Host orchestration
// ---------------------------------------------------------------------------
extern "C" void kernel_launch(void* const* d_in, const int* in_sizes, int n_in,
                              void* d_out, int out_size)
{
    const float* x   = (const float*)d_in[0];
    const float* Wq  = (const float*)d_in[1];
    const float* Wk  = (const float*)d_in[2];
    const float* Wq2 = (const float*)d_in[3];
    const float* Wk2 = (const float*)d_in[4];
    const float* Wv  = (const float*)d_in[5];
    const float* Wo  = (const float*)d_in[6];
    const float* Wp1 = (const float*)d_in[7];
    const float* Wp2 = (const float*)d_in[8];
    const float* Wd  = (const float*)d_in[9];
    const float* bd  = (const float*)d_in[10];
    float* out = (float*)d_out;

    float *h, *q, *k, *q2, *k2, *v, *z, *x1, *h2, *t1, *hid;
    cudaGetSymbolAddress((void**)&h,   g_h);
    cudaGetSymbolAddress((void**)&q,   g_q);
    cudaGetSymbolAddress((void**)&k,   g_k);
    cudaGetSymbolAddress((void**)&q2,  g_q2);
    cudaGetSymbolAddress((void**)&k2,  g_k2);
    cudaGetSymbolAddress((void**)&v,   g_v);
    cudaGetSymbolAddress((void**)&z,   g_z);
    cudaGetSymbolAddress((void**)&x1,  g_x1);
    cudaGetSymbolAddress((void**)&h2,  g_h2);
    cudaGetSymbolAddress((void**)&t1,  g_t1);
    cudaGetSymbolAddress((void**)&hid, g_hid);

    // 1. h = rms(x)
    rms_kernel<<<T_SEQ, 256>>>(x, h);

    // 2. fused projections (one launch, 480 CTAs)
    dim3 gp5(C_DIM / GBN, T_SEQ / GBM, 5);
    gemm_proj5<<<gp5, 256>>>(h, Wq, Wk, Wq2, Wk2, Wv, q, k, q2, k2, v);

    // 3. RoPE
    rope_kernel<<<T_SEQ, N_HEAD * 32>>>(q, k, q2, k2);

    // 4. fused attention -> z  (128-row q tiles, 192 CTAs)
    cudaFuncSetAttribute(attn_kernel, cudaFuncAttributeMaxDynamicSharedMemorySize, ATTN_SMEM);
    attn_kernel<<<dim3(T_SEQ / 128, N_HEAD), 256, ATTN_SMEM>>>(q, k, q2, k2, v, z);

    // 5. x1 = x + z @ Wo^T
    dim3 gp(C_DIM / GBN, T_SEQ / GBM);
    gemm_nt<2><<<gp, 256>>>(z, Wo, x1, T_SEQ, C_DIM, C_DIM, x, nullptr, nullptr);

    // 6. h2 = rms(x1)
    rms_kernel<<<T_SEQ, 256>>>(x1, h2);

    // 7. MLP: t1 = h2@Wp1^T ; hid = (h2@Wp2^T) * t1
    dim3 gm(D_HID / GBN, T_SEQ / GBM);
    gemm_nt<0><<<gm, 256>>>(h2, Wp1, t1,  T_SEQ, D_HID, C_DIM, nullptr, nullptr, nullptr);
    gemm_nt<1><<<gm, 256>>>(h2, Wp2, hid, T_SEQ, D_HID, C_DIM, nullptr, t1, nullptr);

    // 8. out = x1 + hid @ Wd^T + bd
    gemm_nt<3><<<gp, 256>>>(hid, Wd, out, T_SEQ, C_DIM, D_HID, x1, nullptr, bd);
}

// round 7
// speedup vs baseline: 1.7200x; 1.3738x over previous
#include <cuda_runtime.h>
#include <cuda_bf16.h>
#include <cstdint>
#include <cstddef>

// Problem constants
#define T_SEQ 2048
#define C_DIM 768
#define N_HEAD 12
#define D_HEAD 64
#define D_HID 3072

// ---------------------------------------------------------------------------
// Scratch (no cudaMalloc allowed)
// ---------------------------------------------------------------------------
__device__ float g_h  [T_SEQ * C_DIM];
__device__ float g_q  [T_SEQ * C_DIM];
__device__ float g_k  [T_SEQ * C_DIM];
__device__ float g_q2 [T_SEQ * C_DIM];
__device__ float g_k2 [T_SEQ * C_DIM];
__device__ float g_v  [T_SEQ * C_DIM];
__device__ float g_z  [T_SEQ * C_DIM];
__device__ float g_x1 [T_SEQ * C_DIM];
__device__ float g_h2 [T_SEQ * C_DIM];
__device__ float g_t1 [T_SEQ * D_HID];
__device__ float g_hid[T_SEQ * D_HID];

// ---------------------------------------------------------------------------
// RMSNorm: one block per token
// ---------------------------------------------------------------------------
__global__ void rms_kernel(const float* __restrict__ x, float* __restrict__ o)
{
    const int t = blockIdx.x;
    const float* xr = x + (size_t)t * C_DIM;
    float s = 0.f;
    for (int i = threadIdx.x; i < C_DIM; i += 256) {
        float v = xr[i];
        s += v * v;
    }
    #pragma unroll
    for (int off = 16; off; off >>= 1)
        s += __shfl_down_sync(0xffffffffu, s, off);
    __shared__ float ws[8];
    __shared__ float scale_s;
    if ((threadIdx.x & 31) == 0) ws[threadIdx.x >> 5] = s;
    __syncthreads();
    if (threadIdx.x == 0) {
        float tot = 0.f;
        #pragma unroll
        for (int w = 0; w < 8; w++) tot += ws[w];
        scale_s = rsqrtf(tot * (1.0f / C_DIM) + 1e-6f);
    }
    __syncthreads();
    const float sc = scale_s;
    for (int i = threadIdx.x; i < C_DIM; i += 256)
        o[(size_t)t * C_DIM + i] = xr[i] * sc;
}

// ---------------------------------------------------------------------------
// RoPE in-place on q,k,q2,k2.  grid = T, block = H*32 = 384
// ---------------------------------------------------------------------------
__global__ void rope_kernel(float* __restrict__ q, float* __restrict__ k,
                            float* __restrict__ q2, float* __restrict__ k2)
{
    const int t = blockIdx.x;
    const int p = threadIdx.x;        // 0..383
    const int h = p >> 5;
    const int i = p & 31;
    const float inv = expf(-(float)i * (9.210340371976184f / 32.0f));
    const float ang = (float)t * inv;
    float sn, cs;
    sincosf(ang, &sn, &cs);
    const size_t base = (size_t)t * C_DIM + h * D_HEAD;
    {
        float a = q[base + i], b = q[base + 32 + i];
        q[base + i]      = a * cs + b * sn;
        q[base + 32 + i] = -a * sn + b * cs;
    }
    {
        float a = k[base + i], b = k[base + 32 + i];
        k[base + i]      = a * cs + b * sn;
        k[base + 32 + i] = -a * sn + b * cs;
    }
    {
        float a = q2[base + i], b = q2[base + 32 + i];
        q2[base + i]      = a * cs + b * sn;
        q2[base + 32 + i] = -a * sn + b * cs;
    }
    {
        float a = k2[base + i], b = k2[base + 32 + i];
        k2[base + i]      = a * cs + b * sn;
        k2[base + 32 + i] = -a * sn + b * cs;
    }
}

// ---------------------------------------------------------------------------
// tf32 tensor-core GEMM core: C_tile(128x128) = A(128xK) @ B(NxK)^T tile.
// mma.sync.m16n8k8 tf32, 8 warps as 2x4, warp tile 64x32, fp32 accum.
// Smem tiles row-major with stride AROW=20 words -> conflict-free STS.128
// staging AND conflict-free fragment LDS (row*20 mod 32 spans all banks).
// Double-buffered, one barrier per 16-K slab.
// ---------------------------------------------------------------------------
#define GBM 128
#define GBN 128
#define GBK 16
#define AROW 20

struct GemmSmem {
    float As[2][GBM * AROW];
    float Bs[2][GBN * AROW];
};

__device__ __forceinline__ uint32_t f2tf32(float f) {
    uint32_t u;
    asm("cvt.rna.tf32.f32 %0, %1;" : "=r"(u) : "f"(f));
    return u;
}

__device__ __forceinline__ void mma_tf32(float c[4], const uint32_t a[4], const uint32_t b[2]) {
    asm volatile(
        "mma.sync.aligned.m16n8k8.row.col.f32.tf32.tf32.f32 "
        "{%0,%1,%2,%3}, {%4,%5,%6,%7}, {%8,%9}, {%0,%1,%2,%3};"
        : "+f"(c[0]), "+f"(c[1]), "+f"(c[2]), "+f"(c[3])
        : "r"(a[0]), "r"(a[1]), "r"(a[2]), "r"(a[3]), "r"(b[0]), "r"(b[1]));
}

__device__ __forceinline__ void stage_row(float* dst, const float4* s) {
    #pragma unroll
    for (int i = 0; i < 4; i++) {
        float4 v = s[i];
        float4 o = make_float4(__uint_as_float(f2tf32(v.x)), __uint_as_float(f2tf32(v.y)),
                               __uint_as_float(f2tf32(v.z)), __uint_as_float(f2tf32(v.w)));
        *reinterpret_cast<float4*>(dst + i * 4) = o;
    }
}

// acc[mi][nj][4] : warp tile 64x32 = 4x4 m16n8 tiles
__device__ __forceinline__ void gemm_core_mma(
    GemmSmem& sm, const float* __restrict__ Ag, const float* __restrict__ Bg,
    int K, float acc[4][4][4], int tid)
{
    const int lane   = tid & 31;
    const int wid    = tid >> 5;
    const int warp_m = wid & 1;
    const int warp_n = wid >> 1;
    const int g = lane >> 2;
    const int t = lane & 3;
    const int arow0 = warp_m * 64;
    const int bcol0 = warp_n * 32;

    const bool  isA  = tid < 128;
    const int   lrow = isA ? tid : tid - 128;
    const float* gsrc = (isA ? Ag : Bg) + (size_t)lrow * K;

    // prologue: stage slab 0
    {
        float4 pv[4];
        #pragma unroll
        for (int i = 0; i < 4; i++)
            pv[i] = *reinterpret_cast<const float4*>(gsrc + i * 4);
        float* dst = (isA ? sm.As[0] : sm.Bs[0]) + lrow * AROW;
        stage_row(dst, pv);
    }
    __syncthreads();

    const int nslab = K / GBK;
    for (int sIdx = 0; sIdx < nslab; sIdx++) {
        const int cur = sIdx & 1;
        const bool have_next = (sIdx + 1) < nslab;

        float4 pv[4];
        if (have_next) {
            const float* s = gsrc + (sIdx + 1) * GBK;
            #pragma unroll
            for (int i = 0; i < 4; i++)
                pv[i] = *reinterpret_cast<const float4*>(s + i * 4);
        }

        const float* Asb = sm.As[cur];
        const float* Bsb = sm.Bs[cur];
        #pragma unroll
        for (int ks = 0; ks < 2; ks++) {
            const int kb = ks * 8;
            uint32_t a[4][4], b[4][2];
            #pragma unroll
            for (int mi = 0; mi < 4; mi++) {
                const int r = arow0 + mi * 16 + g;
                a[mi][0] = __float_as_uint(Asb[r       * AROW + kb + t]);
                a[mi][1] = __float_as_uint(Asb[(r + 8) * AROW + kb + t]);
                a[mi][2] = __float_as_uint(Asb[r       * AROW + kb + t + 4]);
                a[mi][3] = __float_as_uint(Asb[(r + 8) * AROW + kb + t + 4]);
            }
            #pragma unroll
            for (int nj = 0; nj < 4; nj++) {
                const int c = bcol0 + nj * 8 + g;
                b[nj][0] = __float_as_uint(Bsb[c * AROW + kb + t]);
                b[nj][1] = __float_as_uint(Bsb[c * AROW + kb + t + 4]);
            }
            #pragma unroll
            for (int mi = 0; mi < 4; mi++)
                #pragma unroll
                for (int nj = 0; nj < 4; nj++)
                    mma_tf32(acc[mi][nj], a[mi], b[nj]);
        }

        if (have_next) {
            float* dst = (isA ? sm.As[cur ^ 1] : sm.Bs[cur ^ 1]) + lrow * AROW;
            stage_row(dst, pv);
        }
        __syncthreads();
    }
}

// Epilogue helper: per (mi,nj) tile, rows (r, r+8), cols c..c+1 (float2).
// EPI: 0 = store, 1 = *mul, 2 = +res, 3 = +res +bias
template<int EPI>
__device__ __forceinline__ void gemm_epilogue(
    float* __restrict__ C, const float acc[4][4][4],
    int row0, int col0, int N, int tid,
    const float* __restrict__ res, const float* __restrict__ mul,
    const float* __restrict__ bias)
{
    const int lane   = tid & 31;
    const int wid    = tid >> 5;
    const int warp_m = wid & 1;
    const int warp_n = wid >> 1;
    const int g = lane >> 2;
    const int t = lane & 3;

    #pragma unroll
    for (int mi = 0; mi < 4; mi++) {
        #pragma unroll
        for (int nj = 0; nj < 4; nj++) {
            const size_t r0 = (size_t)row0 + warp_m * 64 + mi * 16 + g;
            const size_t c  = (size_t)col0 + warp_n * 32 + nj * 8 + t * 2;
            #pragma unroll
            for (int half = 0; half < 2; half++) {
                const size_t r = r0 + half * 8;
                float2 v = make_float2(acc[mi][nj][half * 2], acc[mi][nj][half * 2 + 1]);
                if (EPI == 1) {
                    float2 m = *reinterpret_cast<const float2*>(mul + r * N + c);
                    v.x *= m.x; v.y *= m.y;
                }
                if (EPI == 2 || EPI == 3) {
                    float2 rr = *reinterpret_cast<const float2*>(res + r * N + c);
                    v.x += rr.x; v.y += rr.y;
                }
                if (EPI == 3) {
                    float2 bb = *reinterpret_cast<const float2*>(bias + c);
                    v.x += bb.x; v.y += bb.y;
                }
                *reinterpret_cast<float2*>(C + r * N + c) = v;
            }
        }
    }
}

template<int EPI>
__global__ __launch_bounds__(256, 2) void gemm_nt(
    const float* __restrict__ A, const float* __restrict__ B, float* __restrict__ C,
    int M, int N, int K,
    const float* __restrict__ res, const float* __restrict__ mul,
    const float* __restrict__ bias)
{
    __shared__ GemmSmem sm;
    const int tid = threadIdx.x;
    const int row0 = blockIdx.y * GBM;
    const int col0 = blockIdx.x * GBN;

    float acc[4][4][4] = {};
    gemm_core_mma(sm, A + (size_t)row0 * K, B + (size_t)col0 * K, K, acc, tid);
    gemm_epilogue<EPI>(C, acc, row0, col0, N, tid, res, mul, bias);
}

// ---------------------------------------------------------------------------
// Fused 5-way projection GEMM: blockIdx.z selects (weight, output) pair.
// ---------------------------------------------------------------------------
__global__ __launch_bounds__(256, 2) void gemm_proj5(
    const float* __restrict__ A,
    const float* __restrict__ W0, const float* __restrict__ W1,
    const float* __restrict__ W2, const float* __restrict__ W3,
    const float* __restrict__ W4,
    float* __restrict__ C0, float* __restrict__ C1,
    float* __restrict__ C2, float* __restrict__ C3,
    float* __restrict__ C4)
{
    __shared__ GemmSmem sm;
    const int tid = threadIdx.x;
    const int row0 = blockIdx.y * GBM;
    const int col0 = blockIdx.x * GBN;

    const float* B;
    float* C;
    switch (blockIdx.z) {
        case 0: B = W0; C = C0; break;
        case 1: B = W1; C = C1; break;
        case 2: B = W2; C = C2; break;
        case 3: B = W3; C = C3; break;
        default: B = W4; C = C4; break;
    }

    float acc[4][4][4] = {};
    gemm_core_mma(sm, A + (size_t)row0 * C_DIM, B + (size_t)col0 * C_DIM, C_DIM, acc, tid);
    gemm_epilogue<0>(C, acc, row0, col0, C_DIM, tid, nullptr, nullptr, nullptr);
}

// ---------------------------------------------------------------------------
// Fused causal "pattern" attention (unchanged from round 6):
//   P = tril( (Q·K^T / 64) * (Q2·K2^T / 64) ),  Z = P @ V
// ---------------------------------------------------------------------------
#define ALD 68
#define ATTN_SMEM ((3 * 128 + 3 * 64) * ALD * (int)sizeof(float))

__global__ __launch_bounds__(256, 1) void attn_kernel(
    const float* __restrict__ q, const float* __restrict__ k,
    const float* __restrict__ q2, const float* __restrict__ k2,
    const float* __restrict__ v, float* __restrict__ z)
{
    extern __shared__ float sm[];
    float* Qs  = sm;
    float* Q2s = Qs  + 128 * ALD;
    float* K1T = Q2s + 128 * ALD;
    float* K2T = K1T + 64 * ALD;
    float* Vs  = K2T + 64 * ALD;
    float* Ps  = Vs  + 64 * ALD;

    const int head = blockIdx.y;
    const int q0   = (gridDim.x - 1 - blockIdx.x) * 128;
    const int tid  = threadIdx.x;
    const int tx   = tid & 15;
    const int ty   = tid >> 4;
    const size_t hb = (size_t)head * D_HEAD;

    for (int f = tid; f < 128 * 16; f += 256) {
        int r  = f >> 4;
        int c4 = (f & 15) * 4;
        *reinterpret_cast<float4*>(&Qs [r * ALD + c4]) =
            *reinterpret_cast<const float4*>(&q [(size_t)(q0 + r) * C_DIM + hb + c4]);
        *reinterpret_cast<float4*>(&Q2s[r * ALD + c4]) =
            *reinterpret_cast<const float4*>(&q2[(size_t)(q0 + r) * C_DIM + hb + c4]);
    }

    float zacc[8][4] = {};

    for (int j0 = 0; j0 <= q0 + 64; j0 += 64) {
        __syncthreads();

        for (int f = tid; f < 64 * 16; f += 256) {
            int r  = f >> 4;
            int c4 = (f & 15) * 4;
            const size_t rowb = (size_t)(j0 + r) * C_DIM + hb + c4;
            float4 kv = *reinterpret_cast<const float4*>(&k [rowb]);
            K1T[(c4 + 0) * ALD + r] = kv.x;
            K1T[(c4 + 1) * ALD + r] = kv.y;
            K1T[(c4 + 2) * ALD + r] = kv.z;
            K1T[(c4 + 3) * ALD + r] = kv.w;
            float4 k2v = *reinterpret_cast<const float4*>(&k2[rowb]);
            K2T[(c4 + 0) * ALD + r] = k2v.x;
            K2T[(c4 + 1) * ALD + r] = k2v.y;
            K2T[(c4 + 2) * ALD + r] = k2v.z;
            K2T[(c4 + 3) * ALD + r] = k2v.w;
            *reinterpret_cast<float4*>(&Vs[r * ALD + c4]) =
                *reinterpret_cast<const float4*>(&v[rowb]);
        }
        __syncthreads();

        float s1[8][4] = {}, s2[8][4] = {};
        #pragma unroll 4
        for (int d = 0; d < 64; d += 4) {
            float kb1[4][4], kb2[4][4];
            #pragma unroll
            for (int u = 0; u < 4; u++) {
                float4 t1 = *reinterpret_cast<const float4*>(&K1T[(d + u) * ALD + tx * 4]);
                kb1[u][0] = t1.x; kb1[u][1] = t1.y; kb1[u][2] = t1.z; kb1[u][3] = t1.w;
                float4 t2 = *reinterpret_cast<const float4*>(&K2T[(d + u) * ALD + tx * 4]);
                kb2[u][0] = t2.x; kb2[u][1] = t2.y; kb2[u][2] = t2.z; kb2[u][3] = t2.w;
            }
            #pragma unroll
            for (int ii = 0; ii < 8; ii++) {
                float4 A1 = *reinterpret_cast<const float4*>(&Qs [(ty * 8 + ii) * ALD + d]);
                float4 A2 = *reinterpret_cast<const float4*>(&Q2s[(ty * 8 + ii) * ALD + d]);
                float a1f[4] = {A1.x, A1.y, A1.z, A1.w};
                float a2f[4] = {A2.x, A2.y, A2.z, A2.w};
                #pragma unroll
                for (int jj = 0; jj < 4; jj++) {
                    #pragma unroll
                    for (int dd = 0; dd < 4; dd++) {
                        s1[ii][jj] += a1f[dd] * kb1[dd][jj];
                        s2[ii][jj] += a2f[dd] * kb2[dd][jj];
                    }
                }
            }
        }

        #pragma unroll
        for (int ii = 0; ii < 8; ii++) {
            const int gi = q0 + ty * 8 + ii;
            float p[4];
            #pragma unroll
            for (int jj = 0; jj < 4; jj++) {
                const int gj = j0 + tx * 4 + jj;
                p[jj] = (gj <= gi) ? s1[ii][jj] * s2[ii][jj] * (1.0f / 4096.0f) : 0.0f;
            }
            *reinterpret_cast<float4*>(&Ps[(ty * 8 + ii) * ALD + tx * 4]) =
                make_float4(p[0], p[1], p[2], p[3]);
        }
        __syncthreads();

        #pragma unroll 4
        for (int j = 0; j < 64; j += 4) {
            float vbf[4][4];
            #pragma unroll
            for (int u = 0; u < 4; u++) {
                float4 t = *reinterpret_cast<const float4*>(&Vs[(j + u) * ALD + tx * 4]);
                vbf[u][0] = t.x; vbf[u][1] = t.y; vbf[u][2] = t.z; vbf[u][3] = t.w;
            }
            #pragma unroll
            for (int ii = 0; ii < 8; ii++) {
                float4 pa = *reinterpret_cast<const float4*>(&Ps[(ty * 8 + ii) * ALD + j]);
                float paf[4] = {pa.x, pa.y, pa.z, pa.w};
                #pragma unroll
                for (int dd = 0; dd < 4; dd++) {
                    zacc[ii][dd] += paf[0] * vbf[0][dd] + paf[1] * vbf[1][dd]
                                  + paf[2] * vbf[2][dd] + paf[3] * vbf[3][dd];
                }
            }
        }
    }

    #pragma unroll
    for (int ii = 0; ii < 8; ii++) {
        float4 o = make_float4(zacc[ii][0], zacc[ii][1], zacc[ii][2], zacc[ii][3]);
        *reinterpret_cast<float4*>(
            &z[(size_t)(q0 + ty * 8 + ii) * C_DIM + hb + tx * 4]) = o;
    }
}

// ---------------------------------------------------------------------------
// Host orchestration
// ---------------------------------------------------------------------------
extern "C" void kernel_launch(void* const* d_in, const int* in_sizes, int n_in,
                              void* d_out, int out_size)
{
    const float* x   = (const float*)d_in[0];
    const float* Wq  = (const float*)d_in[1];
    const float* Wk  = (const float*)d_in[2];
    const float* Wq2 = (const float*)d_in[3];
    const float* Wk2 = (const float*)d_in[4];
    const float* Wv  = (const float*)d_in[5];
    const float* Wo  = (const float*)d_in[6];
    const float* Wp1 = (const float*)d_in[7];
    const float* Wp2 = (const float*)d_in[8];
    const float* Wd  = (const float*)d_in[9];
    const float* bd  = (const float*)d_in[10];
    float* out = (float*)d_out;

    float *h, *q, *k, *q2, *k2, *v, *z, *x1, *h2, *t1, *hid;
    cudaGetSymbolAddress((void**)&h,   g_h);
    cudaGetSymbolAddress((void**)&q,   g_q);
    cudaGetSymbolAddress((void**)&k,   g_k);
    cudaGetSymbolAddress((void**)&q2,  g_q2);
    cudaGetSymbolAddress((void**)&k2,  g_k2);
    cudaGetSymbolAddress((void**)&v,   g_v);
    cudaGetSymbolAddress((void**)&z,   g_z);
    cudaGetSymbolAddress((void**)&x1,  g_x1);
    cudaGetSymbolAddress((void**)&h2,  g_h2);
    cudaGetSymbolAddress((void**)&t1,  g_t1);
    cudaGetSymbolAddress((void**)&hid, g_hid);

    // 1. h = rms(x)
    rms_kernel<<<T_SEQ, 256>>>(x, h);

    // 2. fused projections (one launch, 480 CTAs)
    dim3 gp5(C_DIM / GBN, T_SEQ / GBM, 5);
    gemm_proj5<<<gp5, 256>>>(h, Wq, Wk, Wq2, Wk2, Wv, q, k, q2, k2, v);

    // 3. RoPE
    rope_kernel<<<T_SEQ, N_HEAD * 32>>>(q, k, q2, k2);

    // 4. fused attention -> z  (128-row q tiles, 192 CTAs)
    cudaFuncSetAttribute(attn_kernel, cudaFuncAttributeMaxDynamicSharedMemorySize, ATTN_SMEM);
    attn_kernel<<<dim3(T_SEQ / 128, N_HEAD), 256, ATTN_SMEM>>>(q, k, q2, k2, v, z);

    // 5. x1 = x + z @ Wo^T
    dim3 gp(C_DIM / GBN, T_SEQ / GBM);
    gemm_nt<2><<<gp, 256>>>(z, Wo, x1, T_SEQ, C_DIM, C_DIM, x, nullptr, nullptr);

    // 6. h2 = rms(x1)
    rms_kernel<<<T_SEQ, 256>>>(x1, h2);

    // 7. MLP: t1 = h2@Wp1^T ; hid = (h2@Wp2^T) * t1
    dim3 gm(D_HID / GBN, T_SEQ / GBM);
    gemm_nt<0><<<gm, 256>>>(h2, Wp1, t1,  T_SEQ, D_HID, C_DIM, nullptr, nullptr, nullptr);
    gemm_nt<1><<<gm, 256>>>(h2, Wp2, hid, T_SEQ, D_HID, C_DIM, nullptr, t1, nullptr);

    // 8. out = x1 + hid @ Wd^T + bd
    gemm_nt<3><<<gp, 256>>>(hid, Wd, out, T_SEQ, C_DIM, D_HID, x1, nullptr, bd);
}